// round 2
// baseline (speedup 1.0000x reference)
#include <cuda_runtime.h>
#include <cuda_bf16.h>
#include <cstdint>

#define NP     50000
#define E_RAW  400000
#define E_TOT  450000   // + self loops
#define C1     128      // per-head channels conv1
#define HC1    256      // 2 * C1
#define C2     64       // per-head channels conv2 (mu/ls stacked as 2 heads)
#define HC2    128

// ---------------- scratch layout (floats) ----------------
#define O_T1    0ull                    // [NP, 256]   x@W1
#define O_H     12800000ull             // [NP, 256]   elu output of conv1
#define O_T2    25600000ull             // [NP, 2, 64] h@W_mu | h@W_ls
#define O_A1S   32000000ull             // [NP*2]
#define O_A1D   32100000ull
#define O_A2S   32200000ull
#define O_A2D   32300000ull
#define O_ATT2  32400000ull             // 256: [srcmu64|srcls64|dstmu64|dstls64]
#define O_AGG1  32400256ull             // [NP, 256]
#define O_AGG2  45200256ull             // [NP, 128]
#define O_D1    51600256ull             // [NP*2]
#define O_D2    51700256ull
#define O_M1    51800256ull             // [NP*2]
#define O_M2    51900256ull
#define O_END   52000256ull

__device__ __align__(16) float g_scratch[O_END];

// ---------------- helpers ----------------
__device__ __forceinline__ void atomicMaxFloat(float* addr, float val) {
    if (val >= 0.0f) atomicMax((int*)addr, __float_as_int(val));
    else             atomicMin((unsigned int*)addr, (unsigned int)__float_as_int(val));
}

// ---------------- fill -inf ----------------
__global__ void fill_neginf_kernel(float* p, int n) {
    int i = blockIdx.x * blockDim.x + threadIdx.x;
    if (i < n) p[i] = -__int_as_float(0x7f800000);
}

// ---------------- GEMM: C[M,N] = A[M,K] @ B[K,N], C stored with ldc/coff ----------------
__global__ __launch_bounds__(256) void gemm_kernel(
    const float* __restrict__ A, const float* __restrict__ B, float* __restrict__ C,
    int M, int N, int K, int ldc, int coff)
{
    constexpr int BM = 64, BN = 64, BK = 16;
    __shared__ float As[BK][BM + 4];
    __shared__ float Bs[BK][BN + 4];
    int tid = threadIdx.x;
    int tx = tid & 15, ty = tid >> 4;
    int brow = blockIdx.y * BM, bcol = blockIdx.x * BN;
    float acc[4][4] = {};

    for (int k0 = 0; k0 < K; k0 += BK) {
        #pragma unroll
        for (int i = tid; i < BM * BK; i += 256) {
            int r = i >> 4, c = i & 15;
            int gr = brow + r;
            As[c][r] = (gr < M) ? A[(size_t)gr * K + k0 + c] : 0.0f;
        }
        #pragma unroll
        for (int i = tid; i < BK * BN; i += 256) {
            int r = i >> 6, c = i & 63;
            Bs[r][c] = B[(size_t)(k0 + r) * N + bcol + c];
        }
        __syncthreads();
        #pragma unroll
        for (int kk = 0; kk < BK; kk++) {
            float a[4], b[4];
            #pragma unroll
            for (int i = 0; i < 4; i++) a[i] = As[kk][ty * 4 + i];
            #pragma unroll
            for (int j = 0; j < 4; j++) b[j] = Bs[kk][tx * 4 + j];
            #pragma unroll
            for (int i = 0; i < 4; i++)
                #pragma unroll
                for (int j = 0; j < 4; j++) acc[i][j] += a[i] * b[j];
        }
        __syncthreads();
    }
    #pragma unroll
    for (int i = 0; i < 4; i++) {
        int r = brow + ty * 4 + i;
        if (r < M) {
            #pragma unroll
            for (int j = 0; j < 4; j++)
                C[(size_t)r * ldc + coff + bcol + tx * 4 + j] = acc[i][j];
        }
    }
}

// ---------------- attention coefficients: warp per (node, head); H=2 ----------------
__global__ __launch_bounds__(256) void attn_kernel(
    const float* __restrict__ feat, const float* __restrict__ att_s,
    const float* __restrict__ att_d, float* __restrict__ asrc, float* __restrict__ adst, int C)
{
    int gw = (blockIdx.x * blockDim.x + threadIdx.x) >> 5;
    int lane = threadIdx.x & 31;
    if (gw >= NP * 2) return;
    int n = gw >> 1, h = gw & 1;
    const float* row = feat + (size_t)n * 2 * C + h * C;
    float s = 0.0f, d = 0.0f;
    for (int c = lane; c < C; c += 32) {
        float v = row[c];
        s += v * att_s[h * C + c];
        d += v * att_d[h * C + c];
    }
    #pragma unroll
    for (int o = 16; o; o >>= 1) {
        s += __shfl_xor_sync(0xffffffffu, s, o);
        d += __shfl_xor_sync(0xffffffffu, d, o);
    }
    if (lane == 0) { asrc[gw] = s; adst[gw] = d; }
}

// ---------------- segment max over edges (thread per edge, H=2) ----------------
__global__ __launch_bounds__(256) void edge_max_kernel(
    const int* __restrict__ ei, const float* __restrict__ asrc,
    const float* __restrict__ adst, float* __restrict__ m)
{
    int e = blockIdx.x * blockDim.x + threadIdx.x;
    if (e >= E_TOT) return;
    int s, d;
    if (e < E_RAW) { s = ei[e]; d = ei[E_RAW + e]; } else { s = d = e - E_RAW; }
    #pragma unroll
    for (int h = 0; h < 2; h++) {
        float v = asrc[s * 2 + h] + adst[d * 2 + h];
        v = v > 0.0f ? v : 0.2f * v;
        atomicMaxFloat(&m[d * 2 + h], v);
    }
}

// ---------------- exp + denom + weighted aggregation (warp per edge, H=2) ----------------
__global__ __launch_bounds__(256) void edge_agg_kernel(
    const int* __restrict__ ei, const float* __restrict__ asrc, const float* __restrict__ adst,
    const float* __restrict__ m, const float* __restrict__ feat,
    float* __restrict__ denom, float* __restrict__ agg, int C)
{
    int gw = (blockIdx.x * blockDim.x + threadIdx.x) >> 5;
    int lane = threadIdx.x & 31;
    if (gw >= E_TOT) return;
    int s, d;
    if (gw < E_RAW) { s = ei[gw]; d = ei[E_RAW + gw]; } else { s = d = gw - E_RAW; }

    float e0 = asrc[s * 2 + 0] + adst[d * 2 + 0];
    e0 = e0 > 0.0f ? e0 : 0.2f * e0;
    float w0 = __expf(e0 - m[d * 2 + 0]);
    float e1 = asrc[s * 2 + 1] + adst[d * 2 + 1];
    e1 = e1 > 0.0f ? e1 : 0.2f * e1;
    float w1 = __expf(e1 - m[d * 2 + 1]);

    if (lane == 0) {
        atomicAdd(&denom[d * 2 + 0], w0);
        atomicAdd(&denom[d * 2 + 1], w1);
    }
    int HC = 2 * C;
    const float4* f4 = (const float4*)(feat + (size_t)s * HC);
    float* orow = agg + (size_t)d * HC;
    int Q = HC >> 2;       // float4s per row
    int c1q = C >> 2;      // head boundary in float4 units
    for (int i = lane; i < Q; i += 32) {
        float4 v = f4[i];
        float w = (i < c1q) ? w0 : w1;
        atomicAdd(&orow[4 * i + 0], v.x * w);
        atomicAdd(&orow[4 * i + 1], v.y * w);
        atomicAdd(&orow[4 * i + 2], v.z * w);
        atomicAdd(&orow[4 * i + 3], v.w * w);
    }
}

// ---------------- finalize conv1: h = elu(agg/denom + b1) ----------------
__global__ __launch_bounds__(256) void finalize1_kernel(
    const float* __restrict__ agg, const float* __restrict__ denom,
    const float* __restrict__ b, float* __restrict__ out)
{
    int i = blockIdx.x * blockDim.x + threadIdx.x;  // over NP*HC1/4
    if (i >= NP * (HC1 / 4)) return;
    int n = i / (HC1 / 4);
    int c4 = i % (HC1 / 4);
    int h = (c4 * 4) / C1;
    float inv = 1.0f / (denom[n * 2 + h] + 1e-16f);
    float4 v = ((const float4*)agg)[i];
    float4 bb = ((const float4*)b)[c4];
    float4 r;
    r.x = v.x * inv + bb.x;
    r.y = v.y * inv + bb.y;
    r.z = v.z * inv + bb.z;
    r.w = v.w * inv + bb.w;
    r.x = r.x > 0.0f ? r.x : __expf(r.x) - 1.0f;
    r.y = r.y > 0.0f ? r.y : __expf(r.y) - 1.0f;
    r.z = r.z > 0.0f ? r.z : __expf(r.z) - 1.0f;
    r.w = r.w > 0.0f ? r.w : __expf(r.w) - 1.0f;
    ((float4*)out)[i] = r;
}

// ---------------- pack att vectors for stacked mu/ls "2-head" conv ----------------
__global__ void pack_att2_kernel(const float* sm, const float* sl,
                                 const float* dm, const float* dl, float* att2)
{
    int i = threadIdx.x;  // 256 threads
    if (i < 64)       att2[i]       = sm[i];
    else if (i < 128) att2[i]       = sl[i - 64];
    else if (i < 192) att2[i]       = dm[i - 128];
    else              att2[i]       = dl[i - 192];
}

// ---------------- finalize conv2: write mu then logstd ----------------
__global__ __launch_bounds__(256) void finalize2_kernel(
    const float* __restrict__ agg, const float* __restrict__ denom,
    const float* __restrict__ b_mu, const float* __restrict__ b_ls,
    float* __restrict__ out)
{
    int i = blockIdx.x * blockDim.x + threadIdx.x;  // over NP*128
    if (i >= NP * HC2) return;
    int n = i / HC2;
    int c = i % HC2;
    int h = c >> 6;       // 0 = mu, 1 = logstd
    int cc = c & 63;
    float inv = 1.0f / (denom[n * 2 + h] + 1e-16f);
    float val = agg[i] * inv + (h == 0 ? b_mu[cc] : b_ls[cc]);
    out[(size_t)h * NP * 64 + (size_t)n * 64 + cc] = val;
}

// ---------------- launch ----------------
extern "C" void kernel_launch(void* const* d_in, const int* in_sizes, int n_in,
                              void* d_out, int out_size)
{
    const float* x        = (const float*)d_in[0];
    const int*   ei       = (const int*)  d_in[1];
    const float* W1       = (const float*)d_in[2];
    const float* att_src1 = (const float*)d_in[3];
    const float* att_dst1 = (const float*)d_in[4];
    const float* b1       = (const float*)d_in[5];
    const float* W_mu     = (const float*)d_in[6];
    const float* asrc_mu  = (const float*)d_in[7];
    const float* adst_mu  = (const float*)d_in[8];
    const float* b_mu     = (const float*)d_in[9];
    const float* W_ls     = (const float*)d_in[10];
    const float* asrc_ls  = (const float*)d_in[11];
    const float* adst_ls  = (const float*)d_in[12];
    const float* b_ls     = (const float*)d_in[13];
    float* out = (float*)d_out;

    float* S = nullptr;
    cudaGetSymbolAddress((void**)&S, g_scratch);

    // init: zero agg1/agg2/d1/d2 (contiguous), -inf m1/m2 (contiguous)
    cudaMemsetAsync(S + O_AGG1, 0, (O_M1 - O_AGG1) * sizeof(float), 0);
    fill_neginf_kernel<<<(200000 + 255) / 256, 256>>>(S + O_M1, 200000);

    // conv1: t1 = x @ W1   [50000,128]@[128,256]
    gemm_kernel<<<dim3(4, 782), 256>>>(x, W1, S + O_T1, NP, 256, 128, 256, 0);
    attn_kernel<<<(NP * 2 * 32 + 255) / 256, 256>>>(S + O_T1, att_src1, att_dst1,
                                                    S + O_A1S, S + O_A1D, C1);
    edge_max_kernel<<<(E_TOT + 255) / 256, 256>>>(ei, S + O_A1S, S + O_A1D, S + O_M1);
    edge_agg_kernel<<<(E_TOT * 32 + 255) / 256, 256>>>(ei, S + O_A1S, S + O_A1D, S + O_M1,
                                                       S + O_T1, S + O_D1, S + O_AGG1, C1);
    finalize1_kernel<<<(NP * (HC1 / 4) + 255) / 256, 256>>>(S + O_AGG1, S + O_D1, b1, S + O_H);

    // conv2: t2[:,0,:] = h@W_mu, t2[:,1,:] = h@W_ls  (stacked as 2 heads)
    gemm_kernel<<<dim3(1, 782), 256>>>(S + O_H, W_mu, S + O_T2, NP, 64, 256, 128, 0);
    gemm_kernel<<<dim3(1, 782), 256>>>(S + O_H, W_ls, S + O_T2, NP, 64, 256, 128, 64);
    pack_att2_kernel<<<1, 256>>>(asrc_mu, asrc_ls, adst_mu, adst_ls, S + O_ATT2);
    attn_kernel<<<(NP * 2 * 32 + 255) / 256, 256>>>(S + O_T2, S + O_ATT2, S + O_ATT2 + 128,
                                                    S + O_A2S, S + O_A2D, C2);
    edge_max_kernel<<<(E_TOT + 255) / 256, 256>>>(ei, S + O_A2S, S + O_A2D, S + O_M2);
    edge_agg_kernel<<<(E_TOT * 32 + 255) / 256, 256>>>(ei, S + O_A2S, S + O_A2D, S + O_M2,
                                                       S + O_T2, S + O_D2, S + O_AGG2, C2);
    finalize2_kernel<<<(NP * HC2 + 255) / 256, 256>>>(S + O_AGG2, S + O_D2, b_mu, b_ls, out);
}

// round 3
// speedup vs baseline: 2.1718x; 2.1718x over previous
#include <cuda_runtime.h>
#include <cuda_bf16.h>
#include <cstdint>

#define NP     50000
#define E_RAW  400000
#define E_TOT  450000   // + self loops
#define C1     128
#define HC1    256
#define C2     64
#define HC2    128
#define NBLK   196      // scan blocks: ceil(50000/256)

// ---------------- scratch layout (float units) ----------------
#define O_T1     0ull          // [NP,256]
#define O_H      12800000ull   // [NP,256]
#define O_T2     25600000ull   // [NP,128]
#define O_A1S    32000000ull
#define O_A1D    32100000ull
#define O_A2S    32200000ull
#define O_A2D    32300000ull
#define O_ATT2   32400000ull   // 256
#define O_WCAT   32400256ull   // 256*128
#define O_DEG    32433024ull   // int [50176]
#define O_ROWPTR 32483200ull   // int [50048]
#define O_CURSOR 32533248ull   // int [50048]
#define O_PART   32583296ull   // int [256]
#define O_COL    32583552ull   // int [450000]
#define O_END    33033552ull

__device__ __align__(16) float g_scratch[O_END];

// ================= CSR build =================
__global__ __launch_bounds__(256) void hist_kernel(const int* __restrict__ ei, int* __restrict__ deg) {
    int e = blockIdx.x * blockDim.x + threadIdx.x;
    if (e < E_RAW) atomicAdd(&deg[ei[E_RAW + e]], 1);
}

__global__ __launch_bounds__(256) void scan1_kernel(const int* __restrict__ deg,
                                                    int* __restrict__ rowptr, int* __restrict__ part) {
    __shared__ int sm[256];
    int i = blockIdx.x * 256 + threadIdx.x;
    int v = (i < NP) ? deg[i] + 1 : 0;   // +1 self loop
    sm[threadIdx.x] = v;
    __syncthreads();
    #pragma unroll
    for (int o = 1; o < 256; o <<= 1) {
        int t = (threadIdx.x >= o) ? sm[threadIdx.x - o] : 0;
        __syncthreads();
        sm[threadIdx.x] += t;
        __syncthreads();
    }
    if (i < NP) rowptr[i] = sm[threadIdx.x] - v;    // exclusive within block
    if (threadIdx.x == 255) part[blockIdx.x] = sm[255];
}

__global__ void scan2_kernel(int* part) {  // 1 block, 256 threads, NBLK<=256
    __shared__ int sm[256];
    int v = (threadIdx.x < NBLK) ? part[threadIdx.x] : 0;
    sm[threadIdx.x] = v;
    __syncthreads();
    #pragma unroll
    for (int o = 1; o < 256; o <<= 1) {
        int t = (threadIdx.x >= o) ? sm[threadIdx.x - o] : 0;
        __syncthreads();
        sm[threadIdx.x] += t;
        __syncthreads();
    }
    part[threadIdx.x] = sm[threadIdx.x] - v;        // exclusive
}

__global__ __launch_bounds__(256) void scan3_kernel(const int* __restrict__ part,
                                                    int* __restrict__ rowptr, int* __restrict__ cursor,
                                                    int* __restrict__ col) {
    int i = blockIdx.x * 256 + threadIdx.x;
    if (i < NP) {
        int r = rowptr[i] + part[i >> 8];
        rowptr[i] = r;
        col[r] = i;            // self loop in slot 0
        cursor[i] = r + 1;
    }
    if (i == 0) rowptr[NP] = E_TOT;
}

__global__ __launch_bounds__(256) void scatter_kernel(const int* __restrict__ ei,
                                                      int* __restrict__ cursor, int* __restrict__ col) {
    int e = blockIdx.x * blockDim.x + threadIdx.x;
    if (e >= E_RAW) return;
    int s = ei[e], d = ei[E_RAW + e];
    int p = atomicAdd(&cursor[d], 1);
    col[p] = s;
}

// ================= SGEMM 128x128x8, 256 threads, 8x8/thread =================
__global__ __launch_bounds__(256) void sgemm_kernel(
    const float* __restrict__ A, const float* __restrict__ B, float* __restrict__ C,
    int M, int N, int K)
{
    constexpr int BM = 128, BN = 128, BK = 8;
    __shared__ float As[BK][BM];
    __shared__ float Bs[BK][BN];
    int tid = threadIdx.x;
    int arow = tid >> 1, ak = (tid & 1) * 4;
    int brs = tid >> 5, bcs = (tid & 31) * 4;
    int tx = tid & 15, ty = tid >> 4;
    int gbrow = blockIdx.y * BM, gbcol = blockIdx.x * BN;

    float acc[8][8];
    #pragma unroll
    for (int i = 0; i < 8; i++)
        #pragma unroll
        for (int j = 0; j < 8; j++) acc[i][j] = 0.0f;

    for (int k0 = 0; k0 < K; k0 += BK) {
        int garow = gbrow + arow;
        float4 av = make_float4(0.f, 0.f, 0.f, 0.f);
        if (garow < M) av = *(const float4*)&A[(size_t)garow * K + k0 + ak];
        As[ak + 0][arow] = av.x;
        As[ak + 1][arow] = av.y;
        As[ak + 2][arow] = av.z;
        As[ak + 3][arow] = av.w;
        float4 bv = *(const float4*)&B[(size_t)(k0 + brs) * N + gbcol + bcs];
        *(float4*)&Bs[brs][bcs] = bv;
        __syncthreads();
        #pragma unroll
        for (int kk = 0; kk < BK; kk++) {
            float a[8], b[8];
            *(float4*)&a[0] = *(const float4*)&As[kk][ty * 4];
            *(float4*)&a[4] = *(const float4*)&As[kk][ty * 4 + 64];
            *(float4*)&b[0] = *(const float4*)&Bs[kk][tx * 4];
            *(float4*)&b[4] = *(const float4*)&Bs[kk][tx * 4 + 64];
            #pragma unroll
            for (int i = 0; i < 8; i++)
                #pragma unroll
                for (int j = 0; j < 8; j++) acc[i][j] += a[i] * b[j];
        }
        __syncthreads();
    }
    #pragma unroll
    for (int i = 0; i < 8; i++) {
        int r = gbrow + ty * 4 + (i >> 2) * 64 + (i & 3);
        if (r < M) {
            #pragma unroll
            for (int jh = 0; jh < 2; jh++) {
                float4 v = make_float4(acc[i][jh * 4], acc[i][jh * 4 + 1],
                                       acc[i][jh * 4 + 2], acc[i][jh * 4 + 3]);
                *(float4*)&C[(size_t)r * N + gbcol + tx * 4 + jh * 64] = v;
            }
        }
    }
}

// ================= attention coefficients (warp per node-head, H=2) =================
__global__ __launch_bounds__(256) void attn_kernel(
    const float* __restrict__ feat, const float* __restrict__ att_s,
    const float* __restrict__ att_d, float* __restrict__ asrc, float* __restrict__ adst, int C)
{
    int gw = (blockIdx.x * blockDim.x + threadIdx.x) >> 5;
    int lane = threadIdx.x & 31;
    if (gw >= NP * 2) return;
    int n = gw >> 1, h = gw & 1;
    const float* row = feat + (size_t)n * 2 * C + h * C;
    float s = 0.0f, d = 0.0f;
    for (int c = lane; c < C; c += 32) {
        float v = row[c];
        s += v * att_s[h * C + c];
        d += v * att_d[h * C + c];
    }
    #pragma unroll
    for (int o = 16; o; o >>= 1) {
        s += __shfl_xor_sync(0xffffffffu, s, o);
        d += __shfl_xor_sync(0xffffffffu, d, o);
    }
    if (lane == 0) { asrc[gw] = s; adst[gw] = d; }
}

// ================= fused CSR aggregation, conv1 (HC=256, ELU) =================
__global__ __launch_bounds__(256) void agg1_kernel(
    const int* __restrict__ rowptr, const int* __restrict__ col,
    const float* __restrict__ asrc, const float* __restrict__ adst,
    const float* __restrict__ feat, const float* __restrict__ bias,
    float* __restrict__ out)
{
    int n = (blockIdx.x * blockDim.x + threadIdx.x) >> 5;
    int lane = threadIdx.x & 31;
    if (n >= NP) return;
    int row = rowptr[n], end = rowptr[n + 1];
    float ad0 = adst[2 * n], ad1 = adst[2 * n + 1];

    float m0 = -1e30f, m1 = -1e30f;
    for (int j = row + lane; j < end; j += 32) {
        int s = col[j];
        float e0 = asrc[2 * s] + ad0;     e0 = e0 > 0.f ? e0 : 0.2f * e0;
        float e1 = asrc[2 * s + 1] + ad1; e1 = e1 > 0.f ? e1 : 0.2f * e1;
        m0 = fmaxf(m0, e0); m1 = fmaxf(m1, e1);
    }
    #pragma unroll
    for (int o = 16; o; o >>= 1) {
        m0 = fmaxf(m0, __shfl_xor_sync(0xffffffffu, m0, o));
        m1 = fmaxf(m1, __shfl_xor_sync(0xffffffffu, m1, o));
    }
    int h = lane >> 4;
    float mh = h ? m1 : m0;
    float adh = h ? ad1 : ad0;

    float4 acc0 = make_float4(0.f, 0.f, 0.f, 0.f);
    float4 acc1 = make_float4(0.f, 0.f, 0.f, 0.f);
    float den = 0.0f;
    for (int j = row; j < end; j++) {
        int s = col[j];
        float e = asrc[2 * s + h] + adh;
        e = e > 0.f ? e : 0.2f * e;
        float w = __expf(e - mh);
        den += w;
        const float4* f = (const float4*)(feat + (size_t)s * HC1);
        float4 v0 = f[lane * 2], v1 = f[lane * 2 + 1];
        acc0.x += v0.x * w; acc0.y += v0.y * w; acc0.z += v0.z * w; acc0.w += v0.w * w;
        acc1.x += v1.x * w; acc1.y += v1.y * w; acc1.z += v1.z * w; acc1.w += v1.w * w;
    }
    float inv = 1.0f / (den + 1e-16f);
    int c = lane * 8;
    float4 b0 = *(const float4*)(bias + c);
    float4 b1 = *(const float4*)(bias + c + 4);
    float4 r0, r1;
    r0.x = acc0.x * inv + b0.x; r0.y = acc0.y * inv + b0.y;
    r0.z = acc0.z * inv + b0.z; r0.w = acc0.w * inv + b0.w;
    r1.x = acc1.x * inv + b1.x; r1.y = acc1.y * inv + b1.y;
    r1.z = acc1.z * inv + b1.z; r1.w = acc1.w * inv + b1.w;
    r0.x = r0.x > 0.f ? r0.x : __expf(r0.x) - 1.f;
    r0.y = r0.y > 0.f ? r0.y : __expf(r0.y) - 1.f;
    r0.z = r0.z > 0.f ? r0.z : __expf(r0.z) - 1.f;
    r0.w = r0.w > 0.f ? r0.w : __expf(r0.w) - 1.f;
    r1.x = r1.x > 0.f ? r1.x : __expf(r1.x) - 1.f;
    r1.y = r1.y > 0.f ? r1.y : __expf(r1.y) - 1.f;
    r1.z = r1.z > 0.f ? r1.z : __expf(r1.z) - 1.f;
    r1.w = r1.w > 0.f ? r1.w : __expf(r1.w) - 1.f;
    float* orow = out + (size_t)n * HC1 + c;
    *(float4*)orow = r0;
    *(float4*)(orow + 4) = r1;
}

// ================= fused CSR aggregation, conv2 (HC=128 stacked mu|ls) =================
__global__ __launch_bounds__(256) void agg2_kernel(
    const int* __restrict__ rowptr, const int* __restrict__ col,
    const float* __restrict__ asrc, const float* __restrict__ adst,
    const float* __restrict__ feat, const float* __restrict__ b_mu,
    const float* __restrict__ b_ls, float* __restrict__ out)
{
    int n = (blockIdx.x * blockDim.x + threadIdx.x) >> 5;
    int lane = threadIdx.x & 31;
    if (n >= NP) return;
    int row = rowptr[n], end = rowptr[n + 1];
    float ad0 = adst[2 * n], ad1 = adst[2 * n + 1];

    float m0 = -1e30f, m1 = -1e30f;
    for (int j = row + lane; j < end; j += 32) {
        int s = col[j];
        float e0 = asrc[2 * s] + ad0;     e0 = e0 > 0.f ? e0 : 0.2f * e0;
        float e1 = asrc[2 * s + 1] + ad1; e1 = e1 > 0.f ? e1 : 0.2f * e1;
        m0 = fmaxf(m0, e0); m1 = fmaxf(m1, e1);
    }
    #pragma unroll
    for (int o = 16; o; o >>= 1) {
        m0 = fmaxf(m0, __shfl_xor_sync(0xffffffffu, m0, o));
        m1 = fmaxf(m1, __shfl_xor_sync(0xffffffffu, m1, o));
    }
    int h = lane >> 4;
    float mh = h ? m1 : m0;
    float adh = h ? ad1 : ad0;

    float4 acc = make_float4(0.f, 0.f, 0.f, 0.f);
    float den = 0.0f;
    for (int j = row; j < end; j++) {
        int s = col[j];
        float e = asrc[2 * s + h] + adh;
        e = e > 0.f ? e : 0.2f * e;
        float w = __expf(e - mh);
        den += w;
        const float4* f = (const float4*)(feat + (size_t)s * HC2);
        float4 v = f[lane];
        acc.x += v.x * w; acc.y += v.y * w; acc.z += v.z * w; acc.w += v.w * w;
    }
    float inv = 1.0f / (den + 1e-16f);
    int cc = (lane & 15) * 4;
    const float* bb = h ? b_ls : b_mu;
    float4 b4 = *(const float4*)(bb + cc);
    float4 r;
    r.x = acc.x * inv + b4.x; r.y = acc.y * inv + b4.y;
    r.z = acc.z * inv + b4.z; r.w = acc.w * inv + b4.w;
    *(float4*)(out + (size_t)h * NP * 64 + (size_t)n * 64 + cc) = r;
}

// ================= small packs =================
__global__ void pack_att2_kernel(const float* sm, const float* sl,
                                 const float* dm, const float* dl, float* att2) {
    int i = threadIdx.x;
    if (i < 64)       att2[i] = sm[i];
    else if (i < 128) att2[i] = sl[i - 64];
    else if (i < 192) att2[i] = dm[i - 128];
    else              att2[i] = dl[i - 192];
}

__global__ __launch_bounds__(256) void pack_wcat_kernel(const float* __restrict__ W_mu,
                                                        const float* __restrict__ W_ls,
                                                        float* __restrict__ Wcat) {
    int i = blockIdx.x * 256 + threadIdx.x;   // over 256*128
    if (i >= 256 * 128) return;
    int k = i >> 7, j = i & 127;
    Wcat[i] = (j < 64) ? W_mu[k * 64 + j] : W_ls[k * 64 + (j - 64)];
}

// ================= launch =================
extern "C" void kernel_launch(void* const* d_in, const int* in_sizes, int n_in,
                              void* d_out, int out_size)
{
    const float* x        = (const float*)d_in[0];
    const int*   ei       = (const int*)  d_in[1];
    const float* W1       = (const float*)d_in[2];
    const float* att_src1 = (const float*)d_in[3];
    const float* att_dst1 = (const float*)d_in[4];
    const float* b1       = (const float*)d_in[5];
    const float* W_mu     = (const float*)d_in[6];
    const float* asrc_mu  = (const float*)d_in[7];
    const float* adst_mu  = (const float*)d_in[8];
    const float* b_mu     = (const float*)d_in[9];
    const float* W_ls     = (const float*)d_in[10];
    const float* asrc_ls  = (const float*)d_in[11];
    const float* adst_ls  = (const float*)d_in[12];
    const float* b_ls     = (const float*)d_in[13];
    float* out = (float*)d_out;

    float* S = nullptr;
    cudaGetSymbolAddress((void**)&S, g_scratch);
    int* deg    = (int*)(S + O_DEG);
    int* rowptr = (int*)(S + O_ROWPTR);
    int* cursor = (int*)(S + O_CURSOR);
    int* part   = (int*)(S + O_PART);
    int* col    = (int*)(S + O_COL);

    // ---- CSR build ----
    cudaMemsetAsync(deg, 0, 50176 * sizeof(int), 0);
    hist_kernel<<<(E_RAW + 255) / 256, 256>>>(ei, deg);
    scan1_kernel<<<NBLK, 256>>>(deg, rowptr, part);
    scan2_kernel<<<1, 256>>>(part);
    scan3_kernel<<<NBLK, 256>>>(part, rowptr, cursor, col);
    scatter_kernel<<<(E_RAW + 255) / 256, 256>>>(ei, cursor, col);

    // ---- conv1 ----
    sgemm_kernel<<<dim3(2, 391), 256>>>(x, W1, S + O_T1, NP, 256, 128);
    attn_kernel<<<(NP * 2 * 32 + 255) / 256, 256>>>(S + O_T1, att_src1, att_dst1,
                                                    S + O_A1S, S + O_A1D, C1);
    agg1_kernel<<<(NP * 32 + 255) / 256, 256>>>(rowptr, col, S + O_A1S, S + O_A1D,
                                                S + O_T1, b1, S + O_H);

    // ---- conv2 (mu|ls stacked) ----
    pack_wcat_kernel<<<128, 256>>>(W_mu, W_ls, S + O_WCAT);
    sgemm_kernel<<<dim3(1, 391), 256>>>(S + O_H, S + O_WCAT, S + O_T2, NP, 128, 256);
    pack_att2_kernel<<<1, 256>>>(asrc_mu, asrc_ls, adst_mu, adst_ls, S + O_ATT2);
    attn_kernel<<<(NP * 2 * 32 + 255) / 256, 256>>>(S + O_T2, S + O_ATT2, S + O_ATT2 + 128,
                                                    S + O_A2S, S + O_A2D, C2);
    agg2_kernel<<<(NP * 32 + 255) / 256, 256>>>(rowptr, col, S + O_A2S, S + O_A2D,
                                                S + O_T2, b_mu, b_ls, out);
}